// round 4
// baseline (speedup 1.0000x reference)
#include <cuda_runtime.h>
#include <stdint.h>
#include <math.h>

// dims: b=4, n=4096, d=128, hid=512, CHUNK=64
#define NTOK 16384
#define D 128
#define HID 512
#define NC 64
#define BATCH 4
#define SLICES 8
#define STG 9216                 // words per stage (A 4608 + B 4608)
#define SMEM_DYN (2*STG*4)       // 73728 bytes

// ---------------- scratch ----------------
__device__ float g_K [NTOK*D];
__device__ float g_V [NTOK*D];
__device__ float g_Q [NTOK*D];
__device__ float g_A [NTOK*HID];
__device__ float g_GP[NTOK*HID];
__device__ float g_dH[NTOK*D];
__device__ float g_dZ[NTOK*HID];
__device__ float g_A2[NTOK*HID];
__device__ float g_lrv [BATCH*NC];
__device__ float g_keep[BATCH*NC];
__device__ float g_eta [BATCH*NC];
__device__ float g_coef[BATCH*NC];
__device__ float g_gfp[128*D];
__device__ float g_gf [BATCH*D];
__device__ float g_w1p[BATCH*SLICES*D*HID];
__device__ float g_w2p[BATCH*SLICES*HID*D];
__device__ float g_w1f[BATCH*D*HID];
__device__ float g_w2f[BATCH*HID*D];

// ---------------- helpers ----------------
__device__ __forceinline__ float sigm(float x){ return 1.f/(1.f+expf(-x)); }
__device__ __forceinline__ void gelu_both(float x, float& a, float& gp){
    const float c0 = 0.7978845608028654f, c1 = 0.044715f;
    float x2 = x*x;
    float t = tanhf(c0*x*(1.f + c1*x2));
    a  = 0.5f*x*(1.f + t);
    gp = 0.5f*(1.f + t) + 0.5f*x*(1.f - t*t)*c0*(1.f + 3.f*c1*x2);
}
__device__ __forceinline__ float gelu_f(float x){
    const float c0 = 0.7978845608028654f, c1 = 0.044715f;
    float t = tanhf(c0*x*(1.f + c1*x*x));
    return 0.5f*x*(1.f + t);
}
__device__ __forceinline__ uint32_t cvt_tf32(float x){
    uint32_t r; asm("cvt.rna.tf32.f32 %0, %1;" : "=r"(r) : "f"(x)); return r;
}
__device__ __forceinline__ void mma8(float& c0, float& c1, float& c2, float& c3,
                                     uint32_t a0, uint32_t a1, uint32_t a2, uint32_t a3,
                                     uint32_t b0, uint32_t b1){
    asm volatile("mma.sync.aligned.m16n8k8.row.col.f32.tf32.tf32.f32 "
                 "{%0,%1,%2,%3}, {%4,%5,%6,%7}, {%8,%9}, {%0,%1,%2,%3};"
                 : "+f"(c0), "+f"(c1), "+f"(c2), "+f"(c3)
                 : "r"(a0), "r"(a1), "r"(a2), "r"(a3), "r"(b0), "r"(b1));
}

// ------------- pipelined warp-mma GEMM core: 128x128 tile, BK=32, 256 thr -------
// 8 warps = 4(m) x 2(n); warp tile 32x64 = 2 mtiles x 8 ntiles of m16n8k8.
// AL=0: A smem [m][k] stride 36;  AL=1: A smem [k][m] stride 136 (free transpose)
// BL=0: B smem [k][n] stride 136; BL=1: B smem [n][k] stride 36  (free transpose)

template<int AL, int BL>
__device__ __forceinline__ void ldg_chunk(const float* __restrict__ Ag, int lda,
                                          const float* __restrict__ Bg, int ldb,
                                          int k0, int tid, float4 pa[4], float4 pb[4]) {
    #pragma unroll
    for (int i = 0; i < 4; i++) {
        int idx4 = tid + i*256;
        if (AL == 0) { int r = idx4 >> 3, c4 = idx4 & 7;
            pa[i] = *reinterpret_cast<const float4*>(Ag + (size_t)r*lda + k0 + c4*4); }
        else         { int r = idx4 >> 5, c4 = idx4 & 31;
            pa[i] = *reinterpret_cast<const float4*>(Ag + (size_t)(k0+r)*lda + c4*4); }
        if (BL == 0) { int r = idx4 >> 5, c4 = idx4 & 31;
            pb[i] = *reinterpret_cast<const float4*>(Bg + (size_t)(k0+r)*ldb + c4*4); }
        else         { int r = idx4 >> 3, c4 = idx4 & 7;
            pb[i] = *reinterpret_cast<const float4*>(Bg + (size_t)r*ldb + k0 + c4*4); }
    }
}

template<int AL, int BL>
__device__ __forceinline__ void sts_chunk(uint32_t* As, uint32_t* Bs, int tid,
                                          const float4 pa[4], const float4 pb[4]) {
    #pragma unroll
    for (int i = 0; i < 4; i++) {
        int idx4 = tid + i*256;
        uint32_t oa, ob;
        if (AL == 0) { int r = idx4 >> 3, c4 = idx4 & 7;  oa = r*36  + c4*4; }
        else         { int r = idx4 >> 5, c4 = idx4 & 31; oa = r*136 + c4*4; }
        if (BL == 0) { int r = idx4 >> 5, c4 = idx4 & 31; ob = r*136 + c4*4; }
        else         { int r = idx4 >> 3, c4 = idx4 & 7;  ob = r*36  + c4*4; }
        As[oa+0] = cvt_tf32(pa[i].x); As[oa+1] = cvt_tf32(pa[i].y);
        As[oa+2] = cvt_tf32(pa[i].z); As[oa+3] = cvt_tf32(pa[i].w);
        Bs[ob+0] = cvt_tf32(pb[i].x); Bs[ob+1] = cvt_tf32(pb[i].y);
        Bs[ob+2] = cvt_tf32(pb[i].z); Bs[ob+3] = cvt_tf32(pb[i].w);
    }
}

template<int AL, int BL>
__device__ __forceinline__ void ld_frags(const uint32_t* As, const uint32_t* Bs, int k,
                                         int wm, int wn, int group, int tg,
                                         uint32_t af[2][4], uint32_t bf[8][2]) {
    #pragma unroll
    for (int mt = 0; mt < 2; mt++) {
        int r = wm*32 + mt*16 + group;
        if (AL == 0) {
            af[mt][0] = As[(r  )*36 + k + tg];
            af[mt][1] = As[(r+8)*36 + k + tg];
            af[mt][2] = As[(r  )*36 + k + tg + 4];
            af[mt][3] = As[(r+8)*36 + k + tg + 4];
        } else {
            af[mt][0] = As[(k+tg  )*136 + r];
            af[mt][1] = As[(k+tg  )*136 + r + 8];
            af[mt][2] = As[(k+tg+4)*136 + r];
            af[mt][3] = As[(k+tg+4)*136 + r + 8];
        }
    }
    #pragma unroll
    for (int nt = 0; nt < 8; nt++) {
        int cb = wn*64 + nt*8 + group;
        if (BL == 0) { bf[nt][0] = Bs[(k+tg)*136 + cb]; bf[nt][1] = Bs[(k+tg+4)*136 + cb]; }
        else         { bf[nt][0] = Bs[cb*36 + k + tg];  bf[nt][1] = Bs[cb*36 + k + tg + 4]; }
    }
}

__device__ __forceinline__ void mma_step(float acc[2][8][4],
                                         const uint32_t af[2][4], const uint32_t bf[8][2]) {
    #pragma unroll
    for (int nt = 0; nt < 8; nt++)
        #pragma unroll
        for (int mt = 0; mt < 2; mt++)
            mma8(acc[mt][nt][0], acc[mt][nt][1], acc[mt][nt][2], acc[mt][nt][3],
                 af[mt][0], af[mt][1], af[mt][2], af[mt][3], bf[nt][0], bf[nt][1]);
}

template<int AL, int BL, int NCH>
__device__ __forceinline__ void mma_core(const float* __restrict__ Ag, int lda,
                                         const float* __restrict__ Bg, int ldb,
                                         float acc[2][8][4], uint32_t* smp) {
    const int tid = threadIdx.x;
    const int lane = tid & 31, group = lane >> 2, tg = lane & 3;
    const int wid = tid >> 5, wm = wid & 3, wn = wid >> 2;
    float4 pa[4], pb[4];

    ldg_chunk<AL,BL>(Ag, lda, Bg, ldb, 0, tid, pa, pb);
    sts_chunk<AL,BL>(smp, smp + 4608, tid, pa, pb);
    __syncthreads();

    uint32_t af[2][2][4], bf[2][8][2];
    #pragma unroll 1
    for (int c = 0; c < NCH; c++) {
        const uint32_t* As = smp + (c & 1)*STG;
        const uint32_t* Bs = As + 4608;
        uint32_t* An = smp + ((c + 1) & 1)*STG;
        if (c + 1 < NCH) ldg_chunk<AL,BL>(Ag, lda, Bg, ldb, (c+1)*32, tid, pa, pb);
        ld_frags<AL,BL>(As, Bs, 0,  wm, wn, group, tg, af[0], bf[0]);
        ld_frags<AL,BL>(As, Bs, 8,  wm, wn, group, tg, af[1], bf[1]);
        mma_step(acc, af[0], bf[0]);
        ld_frags<AL,BL>(As, Bs, 16, wm, wn, group, tg, af[0], bf[0]);
        mma_step(acc, af[1], bf[1]);
        if (c + 1 < NCH) sts_chunk<AL,BL>(An, An + 4608, tid, pa, pb);
        ld_frags<AL,BL>(As, Bs, 24, wm, wn, group, tg, af[1], bf[1]);
        mma_step(acc, af[0], bf[0]);
        mma_step(acc, af[1], bf[1]);
        __syncthreads();
    }
}

// epilogue index helpers (row/col local to 128x128 tile)
#define ROW_OF(mt, h)  (wm*32 + (mt)*16 + group + 8*(h))
#define COL_OF(nt)     (wn*64 + (nt)*8 + 2*tg)

// ---------------- scalar kernels ----------------
__device__ __forceinline__ float bred128(float v){
    __shared__ float wr[4];
    #pragma unroll
    for (int o = 16; o > 0; o >>= 1) v += __shfl_down_sync(0xffffffffu, v, o);
    int tid = threadIdx.x;
    if ((tid & 31) == 0) wr[tid >> 5] = v;
    __syncthreads();
    float r = wr[0] + wr[1] + wr[2] + wr[3];
    __syncthreads();
    return r;
}
__global__ void k_dots(const float* __restrict__ seq,
                       const float* __restrict__ wlr,  const float* __restrict__ blr,
                       const float* __restrict__ wdec, const float* __restrict__ bdec,
                       const float* __restrict__ wmom, const float* __restrict__ bmom) {
    int b = blockIdx.x >> 6, c = blockIdx.x & 63;
    int tid = threadIdx.x;
    float x = seq[((size_t)b*4096 + c*64)*D + tid];
    float s1 = bred128(x*wlr[tid]);
    float s2 = bred128(x*wdec[tid]);
    float s3 = bred128(x*wmom[tid]);
    if (tid == 0) {
        g_lrv [b*NC + c] = sigm(s1 + blr[0]);
        g_keep[b*NC + c] = 1.f - sigm(s2 + bdec[0]);
        g_eta [b*NC + c] = sigm(s3 + bmom[0]);
    }
}
__global__ void k_coef() {
    int b = threadIdx.x;
    if (b >= BATCH) return;
    float Av = 1.f, Bv = 1.f;
    g_coef[b*NC + NC-1] = -g_lrv[b*NC + NC-1]*(2.f/128.f);
    for (int j = NC-2; j >= 0; j--) {
        Bv *= g_keep[b*NC + j+1];
        Av  = Bv + g_eta[b*NC + j+1]*Av;
        g_coef[b*NC + j] = -Av*g_lrv[b*NC + j]*(2.f/128.f);
    }
}

// ---------------- G1: K/V/Q = seq @ W ----------------
__global__ __launch_bounds__(256) void g1_proj(const float* __restrict__ seq,
                                               const float* __restrict__ wk,
                                               const float* __restrict__ wv,
                                               const float* __restrict__ wq) {
    extern __shared__ uint32_t smp[];
    const float* W = (blockIdx.z == 0) ? wk : (blockIdx.z == 1 ? wv : wq);
    float* O = (blockIdx.z == 0) ? g_K : (blockIdx.z == 1 ? g_V : g_Q);
    int row0 = blockIdx.x * 128;
    float acc[2][8][4] = {};
    mma_core<0,0,4>(seq + (size_t)row0*D, D, W, D, acc, smp);
    const int tid = threadIdx.x, lane = tid & 31, group = lane >> 2, tg = lane & 3;
    const int wid = tid >> 5, wm = wid & 3, wn = wid >> 2;
    #pragma unroll
    for (int mt = 0; mt < 2; mt++)
        #pragma unroll
        for (int h = 0; h < 2; h++) {
            int tok = row0 + ROW_OF(mt, h);
            #pragma unroll
            for (int nt = 0; nt < 8; nt++)
                *reinterpret_cast<float2*>(O + (size_t)tok*D + COL_OF(nt)) =
                    make_float2(acc[mt][nt][2*h], acc[mt][nt][2*h+1]);
        }
}

// ---------------- G2: Z = K @ w1 -> gelu, gelu' ----------------
__global__ __launch_bounds__(256) void g2_zgelu(const float* __restrict__ w1) {
    extern __shared__ uint32_t smp[];
    int row0 = blockIdx.x*128, n0 = blockIdx.y*128;
    float acc[2][8][4] = {};
    mma_core<0,0,4>(g_K + (size_t)row0*D, D, w1 + n0, HID, acc, smp);
    const int tid = threadIdx.x, lane = tid & 31, group = lane >> 2, tg = lane & 3;
    const int wid = tid >> 5, wm = wid & 3, wn = wid >> 2;
    #pragma unroll
    for (int mt = 0; mt < 2; mt++)
        #pragma unroll
        for (int h = 0; h < 2; h++) {
            int tok = row0 + ROW_OF(mt, h);
            size_t base = (size_t)tok*HID + n0;
            #pragma unroll
            for (int nt = 0; nt < 8; nt++) {
                int cc = COL_OF(nt);
                float a0, p0, a1, p1;
                gelu_both(acc[mt][nt][2*h],   a0, p0);
                gelu_both(acc[mt][nt][2*h+1], a1, p1);
                *reinterpret_cast<float2*>(g_A  + base + cc) = make_float2(a0, a1);
                *reinterpret_cast<float2*>(g_GP + base + cc) = make_float2(p0, p1);
            }
        }
}

// ---------------- G3: H = A @ w2; rmsnorm bwd -> dH, dgamma partial -------------
__global__ __launch_bounds__(256) void g3_hback(const float* __restrict__ w2,
                                                const float* __restrict__ gamma) {
    extern __shared__ uint32_t smp[];
    __shared__ float gam[128];
    const int tid = threadIdx.x;
    if (tid < 128) gam[tid] = gamma[tid];
    int row0 = blockIdx.x * 128;
    float acc[2][8][4] = {};
    mma_core<0,0,16>(g_A + (size_t)row0*HID, HID, w2, D, acc, smp);
    const int lane = tid & 31, group = lane >> 2, tg = lane & 3;
    const int wid = tid >> 5, wm = wid & 3, wn = wid >> 2;
    float* rs = reinterpret_cast<float*>(smp);        // [2][128]
    float* cs = reinterpret_cast<float*>(smp) + 256;  // [4][128]

    #pragma unroll
    for (int mt = 0; mt < 2; mt++)
        #pragma unroll
        for (int h = 0; h < 2; h++) {
            float s = 0;
            #pragma unroll
            for (int nt = 0; nt < 8; nt++)
                s += acc[mt][nt][2*h]*acc[mt][nt][2*h] + acc[mt][nt][2*h+1]*acc[mt][nt][2*h+1];
            s += __shfl_xor_sync(0xffffffffu, s, 1);
            s += __shfl_xor_sync(0xffffffffu, s, 2);
            if (tg == 0) rs[wn*128 + ROW_OF(mt, h)] = s;
        }
    __syncthreads();
    float ir[2][2], cf[2][2];
    #pragma unroll
    for (int mt = 0; mt < 2; mt++)
        #pragma unroll
        for (int h = 0; h < 2; h++) {
            int r = ROW_OF(mt, h);
            ir[mt][h] = rsqrtf((rs[r] + rs[128 + r])*(1.f/128.f) + 1e-6f);
            int tok = row0 + r;
            cf[mt][h] = g_coef[(tok >> 12)*NC + ((tok & 4095) >> 6)];
        }
    __syncthreads();

    #pragma unroll
    for (int mt = 0; mt < 2; mt++)
        #pragma unroll
        for (int h = 0; h < 2; h++) {
            int r = ROW_OF(mt, h), tok = row0 + r;
            float irr = ir[mt][h], cfv = cf[mt][h];
            float dsum = 0;
            #pragma unroll
            for (int nt = 0; nt < 8; nt++) {
                int cc = COL_OF(nt);
                float2 kk = *reinterpret_cast<const float2*>(g_K + (size_t)tok*D + cc);
                float2 vv = *reinterpret_cast<const float2*>(g_V + (size_t)tok*D + cc);
                float hn0 = acc[mt][nt][2*h]*irr,   hn1 = acc[mt][nt][2*h+1]*irr;
                float dp0 = cfv*(hn0*gam[cc] + kk.x - vv.x);
                float dp1 = cfv*(hn1*gam[cc+1] + kk.y - vv.y);
                dsum += dp0*gam[cc]*hn0 + dp1*gam[cc+1]*hn1;
            }
            dsum += __shfl_xor_sync(0xffffffffu, dsum, 1);
            dsum += __shfl_xor_sync(0xffffffffu, dsum, 2);
            if (tg == 0) rs[wn*128 + r] = dsum;
        }
    __syncthreads();

    float colp[8][2] = {};
    #pragma unroll
    for (int mt = 0; mt < 2; mt++)
        #pragma unroll
        for (int h = 0; h < 2; h++) {
            int r = ROW_OF(mt, h), tok = row0 + r;
            float irr = ir[mt][h], cfv = cf[mt][h];
            float rd = (rs[r] + rs[128 + r])*(1.f/128.f);
            #pragma unroll
            for (int nt = 0; nt < 8; nt++) {
                int cc = COL_OF(nt);
                float2 kk = *reinterpret_cast<const float2*>(g_K + (size_t)tok*D + cc);
                float2 vv = *reinterpret_cast<const float2*>(g_V + (size_t)tok*D + cc);
                float hn0 = acc[mt][nt][2*h]*irr,   hn1 = acc[mt][nt][2*h+1]*irr;
                float dp0 = cfv*(hn0*gam[cc] + kk.x - vv.x);
                float dp1 = cfv*(hn1*gam[cc+1] + kk.y - vv.y);
                float o0 = irr*(dp0*gam[cc]   - hn0*rd);
                float o1 = irr*(dp1*gam[cc+1] - hn1*rd);
                *reinterpret_cast<float2*>(g_dH + (size_t)tok*D + cc) = make_float2(o0, o1);
                colp[nt][0] += dp0*hn0;
                colp[nt][1] += dp1*hn1;
            }
        }
    #pragma unroll
    for (int nt = 0; nt < 8; nt++)
        #pragma unroll
        for (int j = 0; j < 2; j++) {
            float v = colp[nt][j];
            v += __shfl_xor_sync(0xffffffffu, v, 4);
            v += __shfl_xor_sync(0xffffffffu, v, 8);
            v += __shfl_xor_sync(0xffffffffu, v, 16);
            if (group == 0) cs[wm*128 + COL_OF(nt) + j] = v;
        }
    __syncthreads();
    if (tid < 128) {
        float s = cs[tid] + cs[128 + tid] + cs[256 + tid] + cs[384 + tid];
        g_gfp[blockIdx.x*128 + tid] = s;
    }
}

// ---------------- G4: dZ = (dH @ w2^T) * GP ----------------
__global__ __launch_bounds__(256) void g4_da(const float* __restrict__ w2) {
    extern __shared__ uint32_t smp[];
    int row0 = blockIdx.x*128, n0 = blockIdx.y*128;
    float acc[2][8][4] = {};
    mma_core<0,1,4>(g_dH + (size_t)row0*D, D, w2 + (size_t)n0*D, D, acc, smp);
    const int tid = threadIdx.x, lane = tid & 31, group = lane >> 2, tg = lane & 3;
    const int wid = tid >> 5, wm = wid & 3, wn = wid >> 2;
    #pragma unroll
    for (int mt = 0; mt < 2; mt++)
        #pragma unroll
        for (int h = 0; h < 2; h++) {
            int tok = row0 + ROW_OF(mt, h);
            size_t base = (size_t)tok*HID + n0;
            #pragma unroll
            for (int nt = 0; nt < 8; nt++) {
                int cc = COL_OF(nt);
                float2 gp = *reinterpret_cast<const float2*>(g_GP + base + cc);
                *reinterpret_cast<float2*>(g_dZ + base + cc) =
                    make_float2(acc[mt][nt][2*h]*gp.x, acc[mt][nt][2*h+1]*gp.y);
            }
        }
}

// ---------------- G5a: w1f partial[z] = K_slice^T @ dZ_slice ----------------
__global__ __launch_bounds__(256) void g5_w1p() {
    extern __shared__ uint32_t smp[];
    int n0 = blockIdx.x * 128;
    int z = blockIdx.z, bh = z >> 3, sl = z & 7;
    int t0 = bh*4096 + sl*512;
    float acc[2][8][4] = {};
    mma_core<1,0,16>(g_K + (size_t)t0*D, D, g_dZ + (size_t)t0*HID + n0, HID, acc, smp);
    const int tid = threadIdx.x, lane = tid & 31, group = lane >> 2, tg = lane & 3;
    const int wid = tid >> 5, wm = wid & 3, wn = wid >> 2;
    float* C = g_w1p + (size_t)z*(D*HID);
    #pragma unroll
    for (int mt = 0; mt < 2; mt++)
        #pragma unroll
        for (int h = 0; h < 2; h++) {
            int r = ROW_OF(mt, h);
            #pragma unroll
            for (int nt = 0; nt < 8; nt++)
                *reinterpret_cast<float2*>(C + (size_t)r*HID + n0 + COL_OF(nt)) =
                    make_float2(acc[mt][nt][2*h], acc[mt][nt][2*h+1]);
        }
}

// ---------------- G5b: w2f partial[z] = A_slice^T @ dH_slice ----------------
__global__ __launch_bounds__(256) void g5_w2p() {
    extern __shared__ uint32_t smp[];
    int m0 = blockIdx.x * 128;
    int z = blockIdx.z, bh = z >> 3, sl = z & 7;
    int t0 = bh*4096 + sl*512;
    float acc[2][8][4] = {};
    mma_core<1,0,16>(g_A + (size_t)t0*HID + m0, HID, g_dH + (size_t)t0*D, D, acc, smp);
    const int tid = threadIdx.x, lane = tid & 31, group = lane >> 2, tg = lane & 3;
    const int wid = tid >> 5, wm = wid & 3, wn = wid >> 2;
    float* C = g_w2p + (size_t)z*(HID*D);
    #pragma unroll
    for (int mt = 0; mt < 2; mt++)
        #pragma unroll
        for (int h = 0; h < 2; h++) {
            int r = m0 + ROW_OF(mt, h);
            #pragma unroll
            for (int nt = 0; nt < 8; nt++)
                *reinterpret_cast<float2*>(C + (size_t)r*D + COL_OF(nt)) =
                    make_float2(acc[mt][nt][2*h], acc[mt][nt][2*h+1]);
        }
}

// ---------------- reduce split-K partials + dgamma ----------------
__global__ void k_reduce() {
    int i = blockIdx.x*256 + threadIdx.x;
    if (i < BATCH*D*HID) {
        int bh = i >> 16, off = i & 65535;
        float s1 = 0, s2 = 0;
        #pragma unroll
        for (int s = 0; s < SLICES; s++) {
            s1 += g_w1p[(size_t)(bh*SLICES + s)*(D*HID) + off];
            s2 += g_w2p[(size_t)(bh*SLICES + s)*(HID*D) + off];
        }
        g_w1f[i] = s1;
        g_w2f[i] = s2;
    }
    if (i < BATCH*D) {
        int bh = i >> 7, col = i & 127;
        float s = 0;
        #pragma unroll
        for (int q = 0; q < 32; q++) s += g_gfp[(bh*32 + q)*128 + col];
        g_gf[i] = s;
    }
}

// ---------------- G6: A2 = gelu(Q @ w1f) ----------------
__global__ __launch_bounds__(256) void g6_z2() {
    extern __shared__ uint32_t smp[];
    int row0 = blockIdx.x*128, n0 = blockIdx.y*128;
    int bh = row0 >> 12;
    float acc[2][8][4] = {};
    mma_core<0,0,4>(g_Q + (size_t)row0*D, D, g_w1f + (size_t)bh*(D*HID) + n0, HID, acc, smp);
    const int tid = threadIdx.x, lane = tid & 31, group = lane >> 2, tg = lane & 3;
    const int wid = tid >> 5, wm = wid & 3, wn = wid >> 2;
    #pragma unroll
    for (int mt = 0; mt < 2; mt++)
        #pragma unroll
        for (int h = 0; h < 2; h++) {
            int tok = row0 + ROW_OF(mt, h);
            size_t base = (size_t)tok*HID + n0;
            #pragma unroll
            for (int nt = 0; nt < 8; nt++) {
                int cc = COL_OF(nt);
                *reinterpret_cast<float2*>(g_A2 + base + cc) =
                    make_float2(gelu_f(acc[mt][nt][2*h]), gelu_f(acc[mt][nt][2*h+1]));
            }
        }
}

// ---------------- G7: out = rmsnorm(A2 @ w2f)*gf + Q ----------------
__global__ __launch_bounds__(256) void g7_out(float* __restrict__ out) {
    extern __shared__ uint32_t smp[];
    __shared__ float gfs[128];
    const int tid = threadIdx.x;
    int row0 = blockIdx.x * 128;
    int bh = row0 >> 12;
    if (tid < 128) gfs[tid] = g_gf[bh*D + tid];
    float acc[2][8][4] = {};
    mma_core<0,0,16>(g_A2 + (size_t)row0*HID, HID, g_w2f + (size_t)bh*(HID*D), D, acc, smp);
    const int lane = tid & 31, group = lane >> 2, tg = lane & 3;
    const int wid = tid >> 5, wm = wid & 3, wn = wid >> 2;
    float* rs = reinterpret_cast<float*>(smp);
    #pragma unroll
    for (int mt = 0; mt < 2; mt++)
        #pragma unroll
        for (int h = 0; h < 2; h++) {
            float s = 0;
            #pragma unroll
            for (int nt = 0; nt < 8; nt++)
                s += acc[mt][nt][2*h]*acc[mt][nt][2*h] + acc[mt][nt][2*h+1]*acc[mt][nt][2*h+1];
            s += __shfl_xor_sync(0xffffffffu, s, 1);
            s += __shfl_xor_sync(0xffffffffu, s, 2);
            if (tg == 0) rs[wn*128 + ROW_OF(mt, h)] = s;
        }
    __syncthreads();
    #pragma unroll
    for (int mt = 0; mt < 2; mt++)
        #pragma unroll
        for (int h = 0; h < 2; h++) {
            int r = ROW_OF(mt, h), tok = row0 + r;
            float irr = rsqrtf((rs[r] + rs[128 + r])*(1.f/128.f) + 1e-6f);
            #pragma unroll
            for (int nt = 0; nt < 8; nt++) {
                int cc = COL_OF(nt);
                float2 qq = *reinterpret_cast<const float2*>(g_Q + (size_t)tok*D + cc);
                *reinterpret_cast<float2*>(out + (size_t)tok*D + cc) =
                    make_float2(acc[mt][nt][2*h]*irr*gfs[cc] + qq.x,
                                acc[mt][nt][2*h+1]*irr*gfs[cc+1] + qq.y);
            }
        }
}

// ---------------- launch ----------------
extern "C" void kernel_launch(void* const* d_in, const int* in_sizes, int n_in,
                              void* d_out, int out_size) {
    (void)in_sizes; (void)n_in; (void)out_size;
    const float* seq  = (const float*)d_in[0];
    const float* wk   = (const float*)d_in[1];
    const float* wv   = (const float*)d_in[2];
    const float* wq   = (const float*)d_in[3];
    const float* wlr  = (const float*)d_in[4];
    const float* blr  = (const float*)d_in[5];
    const float* wdec = (const float*)d_in[6];
    const float* bdec = (const float*)d_in[7];
    const float* wmom = (const float*)d_in[8];
    const float* bmom = (const float*)d_in[9];
    const float* gamma= (const float*)d_in[10];
    const float* w1   = (const float*)d_in[11];
    const float* w2   = (const float*)d_in[12];
    float* out = (float*)d_out;

    cudaFuncSetAttribute(g1_proj,  cudaFuncAttributeMaxDynamicSharedMemorySize, SMEM_DYN);
    cudaFuncSetAttribute(g2_zgelu, cudaFuncAttributeMaxDynamicSharedMemorySize, SMEM_DYN);
    cudaFuncSetAttribute(g3_hback, cudaFuncAttributeMaxDynamicSharedMemorySize, SMEM_DYN);
    cudaFuncSetAttribute(g4_da,    cudaFuncAttributeMaxDynamicSharedMemorySize, SMEM_DYN);
    cudaFuncSetAttribute(g5_w1p,   cudaFuncAttributeMaxDynamicSharedMemorySize, SMEM_DYN);
    cudaFuncSetAttribute(g5_w2p,   cudaFuncAttributeMaxDynamicSharedMemorySize, SMEM_DYN);
    cudaFuncSetAttribute(g6_z2,    cudaFuncAttributeMaxDynamicSharedMemorySize, SMEM_DYN);
    cudaFuncSetAttribute(g7_out,   cudaFuncAttributeMaxDynamicSharedMemorySize, SMEM_DYN);

    k_dots  <<<BATCH*NC, 128>>>(seq, wlr, blr, wdec, bdec, wmom, bmom);
    k_coef  <<<1, 32>>>();
    g1_proj <<<dim3(NTOK/128, 1, 3), 256, SMEM_DYN>>>(seq, wk, wv, wq);
    g2_zgelu<<<dim3(NTOK/128, HID/128), 256, SMEM_DYN>>>(w1);
    g3_hback<<<NTOK/128, 256, SMEM_DYN>>>(w2, gamma);
    g4_da   <<<dim3(NTOK/128, HID/128), 256, SMEM_DYN>>>(w2);
    g5_w1p  <<<dim3(HID/128, 1, BATCH*SLICES), 256, SMEM_DYN>>>();
    g5_w2p  <<<dim3(HID/128, 1, BATCH*SLICES), 256, SMEM_DYN>>>();
    k_reduce<<<(BATCH*D*HID)/256, 256>>>();
    g6_z2   <<<dim3(NTOK/128, HID/128), 256, SMEM_DYN>>>();
    g7_out  <<<NTOK/128, 256, SMEM_DYN>>>(out);
}

// round 5
// speedup vs baseline: 1.1569x; 1.1569x over previous
#include <cuda_runtime.h>
#include <stdint.h>
#include <math.h>

// dims: b=4, n=4096, d=128, hid=512, CHUNK=64
#define NTOK 16384
#define D 128
#define HID 512
#define NC 64
#define BATCH 4
#define SLICES 8
#define NTHR 512
#define STG 9216                 // words per stage (A 4608 + B 4608)
#define SMEM_DYN (2*STG*4)       // 73728 bytes

// ---------------- scratch ----------------
__device__ float g_K [NTOK*D];
__device__ float g_V [NTOK*D];
__device__ float g_Q [NTOK*D];
__device__ float g_A [NTOK*HID];
__device__ float g_GP[NTOK*HID];
__device__ float g_dH[NTOK*D];
__device__ float g_dZ[NTOK*HID];
__device__ float g_A2[NTOK*HID];
__device__ float g_lrv [BATCH*NC];
__device__ float g_keep[BATCH*NC];
__device__ float g_eta [BATCH*NC];
__device__ float g_coef[BATCH*NC];
__device__ float g_gfp[128*D];
__device__ float g_gf [BATCH*D];
__device__ float g_w1p[BATCH*SLICES*D*HID];
__device__ float g_w2p[BATCH*SLICES*HID*D];
__device__ float g_w1f[BATCH*D*HID];
__device__ float g_w2f[BATCH*HID*D];

// ---------------- helpers ----------------
__device__ __forceinline__ float sigm(float x){ return 1.f/(1.f+expf(-x)); }
__device__ __forceinline__ float tanh_fast(float u){
    float e = __expf(2.f*u);
    return 1.f - __fdividef(2.f, e + 1.f);
}
__device__ __forceinline__ void gelu_both(float x, float& a, float& gp){
    const float c0 = 0.7978845608028654f, c1 = 0.044715f;
    float x2 = x*x;
    float t = tanh_fast(c0*x*(1.f + c1*x2));
    a  = 0.5f*x*(1.f + t);
    gp = 0.5f*(1.f + t) + 0.5f*x*(1.f - t*t)*c0*(1.f + 3.f*c1*x2);
}
__device__ __forceinline__ float gelu_f(float x){
    float t = tanh_fast(0.7978845608028654f*x*(1.f + 0.044715f*x*x));
    return 0.5f*x*(1.f + t);
}
__device__ __forceinline__ uint32_t cvt_tf32(float x){
    uint32_t r; asm("cvt.rna.tf32.f32 %0, %1;" : "=r"(r) : "f"(x)); return r;
}
__device__ __forceinline__ void mma8(float& c0, float& c1, float& c2, float& c3,
                                     uint32_t a0, uint32_t a1, uint32_t a2, uint32_t a3,
                                     uint32_t b0, uint32_t b1){
    asm volatile("mma.sync.aligned.m16n8k8.row.col.f32.tf32.tf32.f32 "
                 "{%0,%1,%2,%3}, {%4,%5,%6,%7}, {%8,%9}, {%0,%1,%2,%3};"
                 : "+f"(c0), "+f"(c1), "+f"(c2), "+f"(c3)
                 : "r"(a0), "r"(a1), "r"(a2), "r"(a3), "r"(b0), "r"(b1));
}

// ------------- pipelined warp-mma GEMM core: 128x128 tile, BK=32, 512 thr -------
// 16 warps = 4(m) x 4(n); warp tile 32x32 = 2 mtiles x 4 ntiles of m16n8k8.
// AL=0: A smem [m][k] stride 36;  AL=1: A smem [k][m] stride 136 (free transpose)
// BL=0: B smem [k][n] stride 136; BL=1: B smem [n][k] stride 36  (free transpose)

template<int AL, int BL>
__device__ __forceinline__ void ldg_chunk(const float* __restrict__ Ag, int lda,
                                          const float* __restrict__ Bg, int ldb,
                                          int k0, int tid, float4 pa[2], float4 pb[2]) {
    #pragma unroll
    for (int i = 0; i < 2; i++) {
        int idx4 = tid + i*NTHR;
        if (AL == 0) { int r = idx4 >> 3, c4 = idx4 & 7;
            pa[i] = *reinterpret_cast<const float4*>(Ag + (size_t)r*lda + k0 + c4*4); }
        else         { int r = idx4 >> 5, c4 = idx4 & 31;
            pa[i] = *reinterpret_cast<const float4*>(Ag + (size_t)(k0+r)*lda + c4*4); }
        if (BL == 0) { int r = idx4 >> 5, c4 = idx4 & 31;
            pb[i] = *reinterpret_cast<const float4*>(Bg + (size_t)(k0+r)*ldb + c4*4); }
        else         { int r = idx4 >> 3, c4 = idx4 & 7;
            pb[i] = *reinterpret_cast<const float4*>(Bg + (size_t)r*ldb + k0 + c4*4); }
    }
}

template<int AL, int BL>
__device__ __forceinline__ void sts_chunk(uint32_t* As, uint32_t* Bs, int tid,
                                          const float4 pa[2], const float4 pb[2]) {
    #pragma unroll
    for (int i = 0; i < 2; i++) {
        int idx4 = tid + i*NTHR;
        uint32_t oa, ob;
        if (AL == 0) { int r = idx4 >> 3, c4 = idx4 & 7;  oa = r*36  + c4*4; }
        else         { int r = idx4 >> 5, c4 = idx4 & 31; oa = r*136 + c4*4; }
        if (BL == 0) { int r = idx4 >> 5, c4 = idx4 & 31; ob = r*136 + c4*4; }
        else         { int r = idx4 >> 3, c4 = idx4 & 7;  ob = r*36  + c4*4; }
        As[oa+0] = cvt_tf32(pa[i].x); As[oa+1] = cvt_tf32(pa[i].y);
        As[oa+2] = cvt_tf32(pa[i].z); As[oa+3] = cvt_tf32(pa[i].w);
        Bs[ob+0] = cvt_tf32(pb[i].x); Bs[ob+1] = cvt_tf32(pb[i].y);
        Bs[ob+2] = cvt_tf32(pb[i].z); Bs[ob+3] = cvt_tf32(pb[i].w);
    }
}

template<int AL, int BL>
__device__ __forceinline__ void ld_frags(const uint32_t* As, const uint32_t* Bs, int k,
                                         int wm, int wn, int group, int tg,
                                         uint32_t af[2][4], uint32_t bf[4][2]) {
    #pragma unroll
    for (int mt = 0; mt < 2; mt++) {
        int r = wm*32 + mt*16 + group;
        if (AL == 0) {
            af[mt][0] = As[(r  )*36 + k + tg];
            af[mt][1] = As[(r+8)*36 + k + tg];
            af[mt][2] = As[(r  )*36 + k + tg + 4];
            af[mt][3] = As[(r+8)*36 + k + tg + 4];
        } else {
            af[mt][0] = As[(k+tg  )*136 + r];
            af[mt][1] = As[(k+tg  )*136 + r + 8];
            af[mt][2] = As[(k+tg+4)*136 + r];
            af[mt][3] = As[(k+tg+4)*136 + r + 8];
        }
    }
    #pragma unroll
    for (int nt = 0; nt < 4; nt++) {
        int cb = wn*32 + nt*8 + group;
        if (BL == 0) { bf[nt][0] = Bs[(k+tg)*136 + cb]; bf[nt][1] = Bs[(k+tg+4)*136 + cb]; }
        else         { bf[nt][0] = Bs[cb*36 + k + tg];  bf[nt][1] = Bs[cb*36 + k + tg + 4]; }
    }
}

__device__ __forceinline__ void mma_step(float acc[2][4][4],
                                         const uint32_t af[2][4], const uint32_t bf[4][2]) {
    #pragma unroll
    for (int nt = 0; nt < 4; nt++)
        #pragma unroll
        for (int mt = 0; mt < 2; mt++)
            mma8(acc[mt][nt][0], acc[mt][nt][1], acc[mt][nt][2], acc[mt][nt][3],
                 af[mt][0], af[mt][1], af[mt][2], af[mt][3], bf[nt][0], bf[nt][1]);
}

template<int AL, int BL, int NCH>
__device__ __forceinline__ void mma_core(const float* __restrict__ Ag, int lda,
                                         const float* __restrict__ Bg, int ldb,
                                         float acc[2][4][4], uint32_t* smp) {
    const int tid = threadIdx.x;
    const int lane = tid & 31, group = lane >> 2, tg = lane & 3;
    const int wid = tid >> 5, wm = wid & 3, wn = wid >> 2;
    float4 pa[2], pb[2];

    ldg_chunk<AL,BL>(Ag, lda, Bg, ldb, 0, tid, pa, pb);
    sts_chunk<AL,BL>(smp, smp + 4608, tid, pa, pb);
    __syncthreads();

    uint32_t af[2][2][4], bf[2][4][2];
    #pragma unroll 1
    for (int c = 0; c < NCH; c++) {
        const uint32_t* As = smp + (c & 1)*STG;
        const uint32_t* Bs = As + 4608;
        uint32_t* An = smp + ((c + 1) & 1)*STG;
        if (c + 1 < NCH) ldg_chunk<AL,BL>(Ag, lda, Bg, ldb, (c+1)*32, tid, pa, pb);
        ld_frags<AL,BL>(As, Bs, 0,  wm, wn, group, tg, af[0], bf[0]);
        ld_frags<AL,BL>(As, Bs, 8,  wm, wn, group, tg, af[1], bf[1]);
        mma_step(acc, af[0], bf[0]);
        ld_frags<AL,BL>(As, Bs, 16, wm, wn, group, tg, af[0], bf[0]);
        mma_step(acc, af[1], bf[1]);
        if (c + 1 < NCH) sts_chunk<AL,BL>(An, An + 4608, tid, pa, pb);
        ld_frags<AL,BL>(As, Bs, 24, wm, wn, group, tg, af[1], bf[1]);
        mma_step(acc, af[0], bf[0]);
        mma_step(acc, af[1], bf[1]);
        __syncthreads();
    }
}

// epilogue index helpers (row/col local to 128x128 tile)
#define ROW_OF(mt, h)  (wm*32 + (mt)*16 + group + 8*(h))
#define COL_OF(nt)     (wn*32 + (nt)*8 + 2*tg)

// ---------------- scalar kernels ----------------
__device__ __forceinline__ float bred128(float v){
    __shared__ float wr[4];
    #pragma unroll
    for (int o = 16; o > 0; o >>= 1) v += __shfl_down_sync(0xffffffffu, v, o);
    int tid = threadIdx.x;
    if ((tid & 31) == 0) wr[tid >> 5] = v;
    __syncthreads();
    float r = wr[0] + wr[1] + wr[2] + wr[3];
    __syncthreads();
    return r;
}
__global__ void k_dots(const float* __restrict__ seq,
                       const float* __restrict__ wlr,  const float* __restrict__ blr,
                       const float* __restrict__ wdec, const float* __restrict__ bdec,
                       const float* __restrict__ wmom, const float* __restrict__ bmom) {
    int b = blockIdx.x >> 6, c = blockIdx.x & 63;
    int tid = threadIdx.x;
    float x = seq[((size_t)b*4096 + c*64)*D + tid];
    float s1 = bred128(x*wlr[tid]);
    float s2 = bred128(x*wdec[tid]);
    float s3 = bred128(x*wmom[tid]);
    if (tid == 0) {
        g_lrv [b*NC + c] = sigm(s1 + blr[0]);
        g_keep[b*NC + c] = 1.f - sigm(s2 + bdec[0]);
        g_eta [b*NC + c] = sigm(s3 + bmom[0]);
    }
}
__global__ void k_coef() {
    int b = threadIdx.x;
    if (b >= BATCH) return;
    float Av = 1.f, Bv = 1.f;
    g_coef[b*NC + NC-1] = -g_lrv[b*NC + NC-1]*(2.f/128.f);
    for (int j = NC-2; j >= 0; j--) {
        Bv *= g_keep[b*NC + j+1];
        Av  = Bv + g_eta[b*NC + j+1]*Av;
        g_coef[b*NC + j] = -Av*g_lrv[b*NC + j]*(2.f/128.f);
    }
}

// ---------------- G1: K/V/Q = seq @ W ----------------
__global__ __launch_bounds__(NTHR) void g1_proj(const float* __restrict__ seq,
                                                const float* __restrict__ wk,
                                                const float* __restrict__ wv,
                                                const float* __restrict__ wq) {
    extern __shared__ uint32_t smp[];
    const float* W = (blockIdx.z == 0) ? wk : (blockIdx.z == 1 ? wv : wq);
    float* O = (blockIdx.z == 0) ? g_K : (blockIdx.z == 1 ? g_V : g_Q);
    int row0 = blockIdx.x * 128;
    float acc[2][4][4] = {};
    mma_core<0,0,4>(seq + (size_t)row0*D, D, W, D, acc, smp);
    const int tid = threadIdx.x, lane = tid & 31, group = lane >> 2, tg = lane & 3;
    const int wid = tid >> 5, wm = wid & 3, wn = wid >> 2;
    #pragma unroll
    for (int mt = 0; mt < 2; mt++)
        #pragma unroll
        for (int h = 0; h < 2; h++) {
            int tok = row0 + ROW_OF(mt, h);
            #pragma unroll
            for (int nt = 0; nt < 4; nt++)
                *reinterpret_cast<float2*>(O + (size_t)tok*D + COL_OF(nt)) =
                    make_float2(acc[mt][nt][2*h], acc[mt][nt][2*h+1]);
        }
}

// ---------------- G2: Z = K @ w1 -> gelu, gelu' ----------------
__global__ __launch_bounds__(NTHR) void g2_zgelu(const float* __restrict__ w1) {
    extern __shared__ uint32_t smp[];
    int row0 = blockIdx.x*128, n0 = blockIdx.y*128;
    float acc[2][4][4] = {};
    mma_core<0,0,4>(g_K + (size_t)row0*D, D, w1 + n0, HID, acc, smp);
    const int tid = threadIdx.x, lane = tid & 31, group = lane >> 2, tg = lane & 3;
    const int wid = tid >> 5, wm = wid & 3, wn = wid >> 2;
    #pragma unroll
    for (int mt = 0; mt < 2; mt++)
        #pragma unroll
        for (int h = 0; h < 2; h++) {
            int tok = row0 + ROW_OF(mt, h);
            size_t base = (size_t)tok*HID + n0;
            #pragma unroll
            for (int nt = 0; nt < 4; nt++) {
                int cc = COL_OF(nt);
                float a0, p0, a1, p1;
                gelu_both(acc[mt][nt][2*h],   a0, p0);
                gelu_both(acc[mt][nt][2*h+1], a1, p1);
                *reinterpret_cast<float2*>(g_A  + base + cc) = make_float2(a0, a1);
                *reinterpret_cast<float2*>(g_GP + base + cc) = make_float2(p0, p1);
            }
        }
}

// ---------------- G3: H = A @ w2; rmsnorm bwd -> dH, dgamma partial -------------
__global__ __launch_bounds__(NTHR) void g3_hback(const float* __restrict__ w2,
                                                 const float* __restrict__ gamma) {
    extern __shared__ uint32_t smp[];
    __shared__ float gam[128];
    const int tid = threadIdx.x;
    if (tid < 128) gam[tid] = gamma[tid];
    int row0 = blockIdx.x * 128;
    float acc[2][4][4] = {};
    mma_core<0,0,16>(g_A + (size_t)row0*HID, HID, w2, D, acc, smp);
    const int lane = tid & 31, group = lane >> 2, tg = lane & 3;
    const int wid = tid >> 5, wm = wid & 3, wn = wid >> 2;
    float* rs = reinterpret_cast<float*>(smp);        // [4][128]
    float* cs = reinterpret_cast<float*>(smp) + 512;  // [4][128]

    #pragma unroll
    for (int mt = 0; mt < 2; mt++)
        #pragma unroll
        for (int h = 0; h < 2; h++) {
            float s = 0;
            #pragma unroll
            for (int nt = 0; nt < 4; nt++)
                s += acc[mt][nt][2*h]*acc[mt][nt][2*h] + acc[mt][nt][2*h+1]*acc[mt][nt][2*h+1];
            s += __shfl_xor_sync(0xffffffffu, s, 1);
            s += __shfl_xor_sync(0xffffffffu, s, 2);
            if (tg == 0) rs[wn*128 + ROW_OF(mt, h)] = s;
        }
    __syncthreads();
    float ir[2][2], cf[2][2];
    #pragma unroll
    for (int mt = 0; mt < 2; mt++)
        #pragma unroll
        for (int h = 0; h < 2; h++) {
            int r = ROW_OF(mt, h);
            float s = rs[r] + rs[128 + r] + rs[256 + r] + rs[384 + r];
            ir[mt][h] = rsqrtf(s*(1.f/128.f) + 1e-6f);
            int tok = row0 + r;
            cf[mt][h] = g_coef[(tok >> 12)*NC + ((tok & 4095) >> 6)];
        }
    __syncthreads();

    #pragma unroll
    for (int mt = 0; mt < 2; mt++)
        #pragma unroll
        for (int h = 0; h < 2; h++) {
            int r = ROW_OF(mt, h), tok = row0 + r;
            float irr = ir[mt][h], cfv = cf[mt][h];
            float dsum = 0;
            #pragma unroll
            for (int nt = 0; nt < 4; nt++) {
                int cc = COL_OF(nt);
                float2 kk = *reinterpret_cast<const float2*>(g_K + (size_t)tok*D + cc);
                float2 vv = *reinterpret_cast<const float2*>(g_V + (size_t)tok*D + cc);
                float hn0 = acc[mt][nt][2*h]*irr,   hn1 = acc[mt][nt][2*h+1]*irr;
                float dp0 = cfv*(hn0*gam[cc] + kk.x - vv.x);
                float dp1 = cfv*(hn1*gam[cc+1] + kk.y - vv.y);
                dsum += dp0*gam[cc]*hn0 + dp1*gam[cc+1]*hn1;
            }
            dsum += __shfl_xor_sync(0xffffffffu, dsum, 1);
            dsum += __shfl_xor_sync(0xffffffffu, dsum, 2);
            if (tg == 0) rs[wn*128 + r] = dsum;
        }
    __syncthreads();

    float colp[4][2] = {};
    #pragma unroll
    for (int mt = 0; mt < 2; mt++)
        #pragma unroll
        for (int h = 0; h < 2; h++) {
            int r = ROW_OF(mt, h), tok = row0 + r;
            float irr = ir[mt][h], cfv = cf[mt][h];
            float rd = (rs[r] + rs[128 + r] + rs[256 + r] + rs[384 + r])*(1.f/128.f);
            #pragma unroll
            for (int nt = 0; nt < 4; nt++) {
                int cc = COL_OF(nt);
                float2 kk = *reinterpret_cast<const float2*>(g_K + (size_t)tok*D + cc);
                float2 vv = *reinterpret_cast<const float2*>(g_V + (size_t)tok*D + cc);
                float hn0 = acc[mt][nt][2*h]*irr,   hn1 = acc[mt][nt][2*h+1]*irr;
                float dp0 = cfv*(hn0*gam[cc] + kk.x - vv.x);
                float dp1 = cfv*(hn1*gam[cc+1] + kk.y - vv.y);
                float o0 = irr*(dp0*gam[cc]   - hn0*rd);
                float o1 = irr*(dp1*gam[cc+1] - hn1*rd);
                *reinterpret_cast<float2*>(g_dH + (size_t)tok*D + cc) = make_float2(o0, o1);
                colp[nt][0] += dp0*hn0;
                colp[nt][1] += dp1*hn1;
            }
        }
    __syncthreads();
    #pragma unroll
    for (int nt = 0; nt < 4; nt++)
        #pragma unroll
        for (int j = 0; j < 2; j++) {
            float v = colp[nt][j];
            v += __shfl_xor_sync(0xffffffffu, v, 4);
            v += __shfl_xor_sync(0xffffffffu, v, 8);
            v += __shfl_xor_sync(0xffffffffu, v, 16);
            if (group == 0) cs[wm*128 + COL_OF(nt) + j] = v;
        }
    __syncthreads();
    if (tid < 128) {
        float s = cs[tid] + cs[128 + tid] + cs[256 + tid] + cs[384 + tid];
        g_gfp[blockIdx.x*128 + tid] = s;
    }
}

// ---------------- G4: dZ = (dH @ w2^T) * GP ----------------
__global__ __launch_bounds__(NTHR) void g4_da(const float* __restrict__ w2) {
    extern __shared__ uint32_t smp[];
    int row0 = blockIdx.x*128, n0 = blockIdx.y*128;
    float acc[2][4][4] = {};
    mma_core<0,1,4>(g_dH + (size_t)row0*D, D, w2 + (size_t)n0*D, D, acc, smp);
    const int tid = threadIdx.x, lane = tid & 31, group = lane >> 2, tg = lane & 3;
    const int wid = tid >> 5, wm = wid & 3, wn = wid >> 2;
    #pragma unroll
    for (int mt = 0; mt < 2; mt++)
        #pragma unroll
        for (int h = 0; h < 2; h++) {
            int tok = row0 + ROW_OF(mt, h);
            size_t base = (size_t)tok*HID + n0;
            #pragma unroll
            for (int nt = 0; nt < 4; nt++) {
                int cc = COL_OF(nt);
                float2 gp = *reinterpret_cast<const float2*>(g_GP + base + cc);
                *reinterpret_cast<float2*>(g_dZ + base + cc) =
                    make_float2(acc[mt][nt][2*h]*gp.x, acc[mt][nt][2*h+1]*gp.y);
            }
        }
}

// ---------------- G5a: w1f partial[z] = K_slice^T @ dZ_slice ----------------
__global__ __launch_bounds__(NTHR) void g5_w1p() {
    extern __shared__ uint32_t smp[];
    int n0 = blockIdx.x * 128;
    int z = blockIdx.z, bh = z >> 3, sl = z & 7;
    int t0 = bh*4096 + sl*512;
    float acc[2][4][4] = {};
    mma_core<1,0,16>(g_K + (size_t)t0*D, D, g_dZ + (size_t)t0*HID + n0, HID, acc, smp);
    const int tid = threadIdx.x, lane = tid & 31, group = lane >> 2, tg = lane & 3;
    const int wid = tid >> 5, wm = wid & 3, wn = wid >> 2;
    float* C = g_w1p + (size_t)z*(D*HID);
    #pragma unroll
    for (int mt = 0; mt < 2; mt++)
        #pragma unroll
        for (int h = 0; h < 2; h++) {
            int r = ROW_OF(mt, h);
            #pragma unroll
            for (int nt = 0; nt < 4; nt++)
                *reinterpret_cast<float2*>(C + (size_t)r*HID + n0 + COL_OF(nt)) =
                    make_float2(acc[mt][nt][2*h], acc[mt][nt][2*h+1]);
        }
}

// ---------------- G5b: w2f partial[z] = A_slice^T @ dH_slice ----------------
__global__ __launch_bounds__(NTHR) void g5_w2p() {
    extern __shared__ uint32_t smp[];
    int m0 = blockIdx.x * 128;
    int z = blockIdx.z, bh = z >> 3, sl = z & 7;
    int t0 = bh*4096 + sl*512;
    float acc[2][4][4] = {};
    mma_core<1,0,16>(g_A + (size_t)t0*HID + m0, HID, g_dH + (size_t)t0*D, D, acc, smp);
    const int tid = threadIdx.x, lane = tid & 31, group = lane >> 2, tg = lane & 3;
    const int wid = tid >> 5, wm = wid & 3, wn = wid >> 2;
    float* C = g_w2p + (size_t)z*(HID*D);
    #pragma unroll
    for (int mt = 0; mt < 2; mt++)
        #pragma unroll
        for (int h = 0; h < 2; h++) {
            int r = m0 + ROW_OF(mt, h);
            #pragma unroll
            for (int nt = 0; nt < 4; nt++)
                *reinterpret_cast<float2*>(C + (size_t)r*D + COL_OF(nt)) =
                    make_float2(acc[mt][nt][2*h], acc[mt][nt][2*h+1]);
        }
}

// ---------------- reduce split-K partials + dgamma ----------------
__global__ void k_reduce() {
    int i = blockIdx.x*256 + threadIdx.x;
    if (i < BATCH*D*HID) {
        int bh = i >> 16, off = i & 65535;
        float s1 = 0, s2 = 0;
        #pragma unroll
        for (int s = 0; s < SLICES; s++) {
            s1 += g_w1p[(size_t)(bh*SLICES + s)*(D*HID) + off];
            s2 += g_w2p[(size_t)(bh*SLICES + s)*(HID*D) + off];
        }
        g_w1f[i] = s1;
        g_w2f[i] = s2;
    }
    if (i < BATCH*D) {
        int bh = i >> 7, col = i & 127;
        float s = 0;
        #pragma unroll
        for (int q = 0; q < 32; q++) s += g_gfp[(bh*32 + q)*128 + col];
        g_gf[i] = s;
    }
}

// ---------------- G6: A2 = gelu(Q @ w1f) ----------------
__global__ __launch_bounds__(NTHR) void g6_z2() {
    extern __shared__ uint32_t smp[];
    int row0 = blockIdx.x*128, n0 = blockIdx.y*128;
    int bh = row0 >> 12;
    float acc[2][4][4] = {};
    mma_core<0,0,4>(g_Q + (size_t)row0*D, D, g_w1f + (size_t)bh*(D*HID) + n0, HID, acc, smp);
    const int tid = threadIdx.x, lane = tid & 31, group = lane >> 2, tg = lane & 3;
    const int wid = tid >> 5, wm = wid & 3, wn = wid >> 2;
    #pragma unroll
    for (int mt = 0; mt < 2; mt++)
        #pragma unroll
        for (int h = 0; h < 2; h++) {
            int tok = row0 + ROW_OF(mt, h);
            size_t base = (size_t)tok*HID + n0;
            #pragma unroll
            for (int nt = 0; nt < 4; nt++) {
                int cc = COL_OF(nt);
                *reinterpret_cast<float2*>(g_A2 + base + cc) =
                    make_float2(gelu_f(acc[mt][nt][2*h]), gelu_f(acc[mt][nt][2*h+1]));
            }
        }
}

// ---------------- G7: out = rmsnorm(A2 @ w2f)*gf + Q ----------------
__global__ __launch_bounds__(NTHR) void g7_out(float* __restrict__ out) {
    extern __shared__ uint32_t smp[];
    __shared__ float gfs[128];
    const int tid = threadIdx.x;
    int row0 = blockIdx.x * 128;
    int bh = row0 >> 12;
    if (tid < 128) gfs[tid] = g_gf[bh*D + tid];
    float acc[2][4][4] = {};
    mma_core<0,0,16>(g_A2 + (size_t)row0*HID, HID, g_w2f + (size_t)bh*(HID*D), D, acc, smp);
    const int lane = tid & 31, group = lane >> 2, tg = lane & 3;
    const int wid = tid >> 5, wm = wid & 3, wn = wid >> 2;
    float* rs = reinterpret_cast<float*>(smp);  // [4][128]
    #pragma unroll
    for (int mt = 0; mt < 2; mt++)
        #pragma unroll
        for (int h = 0; h < 2; h++) {
            float s = 0;
            #pragma unroll
            for (int nt = 0; nt < 4; nt++)
                s += acc[mt][nt][2*h]*acc[mt][nt][2*h] + acc[mt][nt][2*h+1]*acc[mt][nt][2*h+1];
            s += __shfl_xor_sync(0xffffffffu, s, 1);
            s += __shfl_xor_sync(0xffffffffu, s, 2);
            if (tg == 0) rs[wn*128 + ROW_OF(mt, h)] = s;
        }
    __syncthreads();
    #pragma unroll
    for (int mt = 0; mt < 2; mt++)
        #pragma unroll
        for (int h = 0; h < 2; h++) {
            int r = ROW_OF(mt, h), tok = row0 + r;
            float s = rs[r] + rs[128 + r] + rs[256 + r] + rs[384 + r];
            float irr = rsqrtf(s*(1.f/128.f) + 1e-6f);
            #pragma unroll
            for (int nt = 0; nt < 4; nt++) {
                int cc = COL_OF(nt);
                float2 qq = *reinterpret_cast<const float2*>(g_Q + (size_t)tok*D + cc);
                *reinterpret_cast<float2*>(out + (size_t)tok*D + cc) =
                    make_float2(acc[mt][nt][2*h]*irr*gfs[cc] + qq.x,
                                acc[mt][nt][2*h+1]*irr*gfs[cc+1] + qq.y);
            }
        }
}

// ---------------- launch ----------------
extern "C" void kernel_launch(void* const* d_in, const int* in_sizes, int n_in,
                              void* d_out, int out_size) {
    (void)in_sizes; (void)n_in; (void)out_size;
    const float* seq  = (const float*)d_in[0];
    const float* wk   = (const float*)d_in[1];
    const float* wv   = (const float*)d_in[2];
    const float* wq   = (const float*)d_in[3];
    const float* wlr  = (const float*)d_in[4];
    const float* blr  = (const float*)d_in[5];
    const float* wdec = (const float*)d_in[6];
    const float* bdec = (const float*)d_in[7];
    const float* wmom = (const float*)d_in[8];
    const float* bmom = (const float*)d_in[9];
    const float* gamma= (const float*)d_in[10];
    const float* w1   = (const float*)d_in[11];
    const float* w2   = (const float*)d_in[12];
    float* out = (float*)d_out;

    cudaFuncSetAttribute(g1_proj,  cudaFuncAttributeMaxDynamicSharedMemorySize, SMEM_DYN);
    cudaFuncSetAttribute(g2_zgelu, cudaFuncAttributeMaxDynamicSharedMemorySize, SMEM_DYN);
    cudaFuncSetAttribute(g3_hback, cudaFuncAttributeMaxDynamicSharedMemorySize, SMEM_DYN);
    cudaFuncSetAttribute(g4_da,    cudaFuncAttributeMaxDynamicSharedMemorySize, SMEM_DYN);
    cudaFuncSetAttribute(g5_w1p,   cudaFuncAttributeMaxDynamicSharedMemorySize, SMEM_DYN);
    cudaFuncSetAttribute(g5_w2p,   cudaFuncAttributeMaxDynamicSharedMemorySize, SMEM_DYN);
    cudaFuncSetAttribute(g6_z2,    cudaFuncAttributeMaxDynamicSharedMemorySize, SMEM_DYN);
    cudaFuncSetAttribute(g7_out,   cudaFuncAttributeMaxDynamicSharedMemorySize, SMEM_DYN);

    k_dots  <<<BATCH*NC, 128>>>(seq, wlr, blr, wdec, bdec, wmom, bmom);
    k_coef  <<<1, 32>>>();
    g1_proj <<<dim3(NTOK/128, 1, 3), NTHR, SMEM_DYN>>>(seq, wk, wv, wq);
    g2_zgelu<<<dim3(NTOK/128, HID/128), NTHR, SMEM_DYN>>>(w1);
    g3_hback<<<NTOK/128, NTHR, SMEM_DYN>>>(w2, gamma);
    g4_da   <<<dim3(NTOK/128, HID/128), NTHR, SMEM_DYN>>>(w2);
    g5_w1p  <<<dim3(HID/128, 1, BATCH*SLICES), NTHR, SMEM_DYN>>>();
    g5_w2p  <<<dim3(HID/128, 1, BATCH*SLICES), NTHR, SMEM_DYN>>>();
    k_reduce<<<(BATCH*D*HID)/256, 256>>>();
    g6_z2   <<<dim3(NTOK/128, HID/128), NTHR, SMEM_DYN>>>();
    g7_out  <<<NTOK/128, NTHR, SMEM_DYN>>>(out);
}